// round 11
// baseline (speedup 1.0000x reference)
#include <cuda_runtime.h>
#include <cuda_fp16.h>
#include <cstdint>
#include <cstddef>

// Problem constants
#define BB 16384
#define DD 256
#define LL 255
#define HH 8

// ---- device scratch ----
// W1 fp16 tiles: [nb 16][ks 16] sub-tiles of 16k x 128n (4KB), causal-masked, swizzled
__device__ __align__(16) __half g_w1t[16 * 16 * 2048];
// x fp16 tiles: [mb 128][kb 4] tiles of 128r x 64k (16KB), swizzled
__device__ __align__(16) __half g_xh[128 * 4 * 8192];
// h1 = tanh(x@W1+b1) fp16: [l 255][b 16384][h 8]
__device__ __align__(16) __half g_h1[(size_t)LL * BB * HH];

// ============================ helpers ============================
__device__ __forceinline__ uint32_t smem_u32(const void* p) {
    uint32_t a;
    asm("{ .reg .u64 t; cvta.to.shared.u64 t, %1; cvt.u32.u64 %0, t; }" : "=r"(a) : "l"(p));
    return a;
}
__device__ __forceinline__ unsigned long long pk2(float a, float b) {
    unsigned long long r;
    asm("mov.b64 %0, {%1, %2};" : "=l"(r) : "f"(a), "f"(b));
    return r;
}
__device__ __forceinline__ void fma2(unsigned long long& d, unsigned long long a, unsigned long long b) {
    asm("fma.rn.f32x2 %0, %1, %2, %0;" : "+l"(d) : "l"(a), "l"(b));
}
__device__ __forceinline__ float2 up2(unsigned long long v) {
    float2 r;
    asm("mov.b64 {%0, %1}, %2;" : "=f"(r.x), "=f"(r.y) : "l"(v));
    return r;
}
__device__ __forceinline__ float ftanha(float v) {
    float r;
    asm("tanh.approx.f32 %0, %1;" : "=f"(r) : "f"(v));
    return r;
}
__device__ __forceinline__ void ldsm4(uint32_t* r, uint32_t a) {
    asm volatile("ldmatrix.sync.aligned.m8n8.x4.shared.b16 {%0,%1,%2,%3}, [%4];"
                 : "=r"(r[0]), "=r"(r[1]), "=r"(r[2]), "=r"(r[3]) : "r"(a));
}
__device__ __forceinline__ void ldsm4t(uint32_t* r, uint32_t a) {
    asm volatile("ldmatrix.sync.aligned.m8n8.x4.trans.shared.b16 {%0,%1,%2,%3}, [%4];"
                 : "=r"(r[0]), "=r"(r[1]), "=r"(r[2]), "=r"(r[3]) : "r"(a));
}
__device__ __forceinline__ void mma_f16(float* d, const uint32_t* a, const uint32_t* b) {
    asm volatile("mma.sync.aligned.m16n8k16.row.col.f32.f16.f16.f32 "
                 "{%0,%1,%2,%3}, {%4,%5,%6,%7}, {%8,%9}, {%0,%1,%2,%3};"
                 : "+f"(d[0]), "+f"(d[1]), "+f"(d[2]), "+f"(d[3])
                 : "r"(a[0]), "r"(a[1]), "r"(a[2]), "r"(a[3]), "r"(b[0]), "r"(b[1]));
}
#define CP_ASYNC16(dst, src) \
    asm volatile("cp.async.cg.shared.global [%0], [%1], 16;" :: "r"(dst), "l"(src))
#define CP_COMMIT() asm volatile("cp.async.commit_group;" ::: "memory")
#define CP_WAIT1()  asm volatile("cp.async.wait_group 1;" ::: "memory")
#define CP_WAIT0()  asm volatile("cp.async.wait_group 0;" ::: "memory")

// ============== prep 1: W1 -> fp16 causal-masked swizzled tiles ==============
__global__ void __launch_bounds__(256) prep_w1(const float* __restrict__ W1) {
    const int nb = blockIdx.x, ks = blockIdx.y;
    __half* dst = g_w1t + (nb * 16 + ks) * 2048;
    #pragma unroll
    for (int i = 0; i < 8; ++i) {
        int e = threadIdx.x + i * 256;        // 0..2047 = 16k x 128n
        int k = e >> 7, nl = e & 127;
        int l = nb * 16 + (nl >> 3), h = nl & 7;
        int kg = ks * 16 + k;
        float v = (l < LL && kg <= l) ? W1[((size_t)l * DD + kg) * HH + h] : 0.f;
        uint32_t off = (uint32_t)k * 128 + ((((nl >> 3) ^ (k & 7))) << 3) + (nl & 7);
        dst[off] = __float2half(v);
    }
}

// ============== prep 2: x -> fp16 swizzled k-chunk tiles ==============
__global__ void __launch_bounds__(256) prep_x(const float* __restrict__ x) {
    int t = blockIdx.x * 256 + threadIdx.x;   // 524288 store-units of 16B
    int kg8 = t & 7;
    int r   = (t >> 3) & 127;
    int kbmb = t >> 10;
    int kb = kbmb & 3, mb = kbmb >> 2;
    const float* src = x + ((size_t)(mb * 128 + r) * DD + kb * 64 + kg8 * 8);
    float4 v0 = *(const float4*)src;
    float4 v1 = *(const float4*)(src + 4);
    __half2 h0 = __floats2half2_rn(v0.x, v0.y);
    __half2 h1 = __floats2half2_rn(v0.z, v0.w);
    __half2 h2 = __floats2half2_rn(v1.x, v1.y);
    __half2 h3 = __floats2half2_rn(v1.z, v1.w);
    uint4 pk = make_uint4(*(uint32_t*)&h0, *(uint32_t*)&h1, *(uint32_t*)&h2, *(uint32_t*)&h3);
    unsigned char* dp = (unsigned char*)g_xh + (size_t)(mb * 4 + kb) * 16384
                      + (uint32_t)r * 128 + (((uint32_t)(kg8 ^ (r & 7))) << 4);
    *(uint4*)dp = pk;
}

// ============== GEMM: h1[l][b][h] = tanh(x @ W1^T + b1), fp16 out ==============
#define ABUF_OFF 0        // 2 x 16KB
#define BBUF_OFF 32768    // 2 x 16KB
#define GEMM_SMEM 65536

extern __shared__ unsigned char gsmem[];

__global__ void __launch_bounds__(256, 2) gemm_kernel(const float* __restrict__ b1) {
    const int tid  = threadIdx.x;
    const int warp = tid >> 5;
    const int lane = tid & 31;
    const int wm   = warp & 3;      // M quarter (32 rows)
    const int wn   = warp >> 2;     // N half (64 cols)
    const int mb   = blockIdx.x & 127;
    const int nb   = blockIdx.x >> 7;
    const int nc   = (nb >> 2) + 1; // causal: # of 64-wide k-chunks needed

    const uint32_t sb = smem_u32(gsmem);

    auto pfA = [&](int kb, int buf) {
        uint32_t dst = sb + ABUF_OFF + (uint32_t)buf * 16384 + (uint32_t)tid * 64;
        const unsigned char* src = (const unsigned char*)g_xh
            + (size_t)(mb * 4 + kb) * 16384 + (size_t)tid * 64;
        #pragma unroll
        for (int i = 0; i < 4; ++i) CP_ASYNC16(dst + i * 16, src + i * 16);
    };
    auto pfB = [&](int kb, int buf) {
        uint32_t dst = sb + BBUF_OFF + (uint32_t)buf * 16384 + (uint32_t)tid * 64;
        const unsigned char* src = (const unsigned char*)g_w1t
            + (size_t)(nb * 16 + kb * 4) * 4096 + (size_t)tid * 64;
        #pragma unroll
        for (int i = 0; i < 4; ++i) CP_ASYNC16(dst + i * 16, src + i * 16);
    };

    pfA(0, 0); pfB(0, 0); CP_COMMIT();
    if (nc > 1) { pfA(1, 1); pfB(1, 1); CP_COMMIT(); }

    float acc[2][8][4];
    #pragma unroll
    for (int mt = 0; mt < 2; ++mt)
        #pragma unroll
        for (int t = 0; t < 8; ++t)
            #pragma unroll
            for (int q = 0; q < 4; ++q) acc[mt][t][q] = 0.f;

    const int arow0 = wm * 32 + (lane & 7) + ((lane >> 3) & 1) * 8;
    const int bk    = (lane & 7) + ((lane >> 3) & 1) * 8;

    for (int kb = 0; kb < nc; ++kb) {
        if (kb < nc - 1) { CP_WAIT1(); } else { CP_WAIT0(); }
        __syncthreads();
        const uint32_t aBuf = sb + ABUF_OFF + (uint32_t)(kb & 1) * 16384;
        const uint32_t bBuf = sb + BBUF_OFF + (uint32_t)(kb & 1) * 16384;
        #pragma unroll
        for (int kt = 0; kt < 4; ++kt) {
            uint32_t af[2][4], bf[4][4];
            uint32_t g = (uint32_t)(2 * kt + (lane >> 4));
            uint32_t offk = ((g ^ (uint32_t)(arow0 & 7)) << 4);
            ldsm4(af[0], aBuf + (uint32_t)arow0 * 128 + offk);
            uint32_t offk1 = ((g ^ (uint32_t)((arow0 + 16) & 7)) << 4);
            ldsm4(af[1], aBuf + (uint32_t)(arow0 + 16) * 128 + offk1);
            #pragma unroll
            for (int p = 0; p < 4; ++p) {
                uint32_t cidx = (uint32_t)(wn * 8 + 2 * p + (lane >> 4));
                ldsm4t(bf[p], bBuf + (uint32_t)kt * 4096 + (uint32_t)bk * 256
                              + ((cidx ^ (uint32_t)(lane & 7)) << 4));
            }
            #pragma unroll
            for (int mt = 0; mt < 2; ++mt)
                #pragma unroll
                for (int p = 0; p < 4; ++p) {
                    mma_f16(acc[mt][2 * p],     af[mt], &bf[p][0]);
                    mma_f16(acc[mt][2 * p + 1], af[mt], &bf[p][2]);
                }
        }
        __syncthreads();
        if (kb + 2 < nc) { pfA(kb + 2, kb & 1); pfB(kb + 2, kb & 1); CP_COMMIT(); }
    }

    // epilogue: tanh(acc + b1) -> fp16 h1, coalesced STG.32
    const int h  = (lane & 3) * 2;
    const int b0 = mb * 128 + wm * 32 + (lane >> 2);
    #pragma unroll
    for (int mt = 0; mt < 2; ++mt) {
        #pragma unroll
        for (int t = 0; t < 8; ++t) {
            int l = nb * 16 + wn * 8 + t;
            if (l < LL) {
                float2 b1v = *(const float2*)(b1 + l * 8 + h);
                int br = b0 + mt * 16;
                __half2 p01 = __floats2half2_rn(ftanha(acc[mt][t][0] + b1v.x),
                                                ftanha(acc[mt][t][1] + b1v.y));
                *(__half2*)(g_h1 + ((size_t)l * BB + br) * HH + h) = p01;
                __half2 p23 = __floats2half2_rn(ftanha(acc[mt][t][2] + b1v.x),
                                                ftanha(acc[mt][t][3] + b1v.y));
                *(__half2*)(g_h1 + ((size_t)l * BB + br + 8) * HH + h) = p23;
            }
        }
    }
}

// ============== pointwise: layers 2-3 + z + log_det ==============
__global__ void __launch_bounds__(256) zmaf_kernel(
    const float* __restrict__ x,   const float* __restrict__ ipar,
    const float* __restrict__ W2,  const float* __restrict__ b2,
    const float* __restrict__ W3,  const float* __restrict__ b3,
    float* __restrict__ out, int out_size)
{
    __shared__ float zst[32 * 17];
    __shared__ float als[256];

    const int tid  = threadIdx.x;
    const int row  = tid & 31;
    const int lq   = tid >> 5;          // warp id = layer offset within step
    const int row0 = blockIdx.x * 32;
    const int rowg = row0 + row;

    float alacc = 0.f;

    for (int jb = 0; jb < 32; ++jb) {
        int l = jb * 8 + lq;
        if (l < LL) {
            // h1: 8 fp16, one LDG.128, fully coalesced across the warp
            uint4 q = *(const uint4*)(g_h1 + ((size_t)l * BB + rowg) * HH);
            float2 f0 = __half22float2(*(__half2*)&q.x);
            float2 f1 = __half22float2(*(__half2*)&q.y);
            float2 f2 = __half22float2(*(__half2*)&q.z);
            float2 f3 = __half22float2(*(__half2*)&q.w);
            float h1v[8] = {f0.x, f0.y, f1.x, f1.y, f2.x, f2.y, f3.x, f3.y};

            // layer 2: a2[k] = b2[k] + sum_h h1[h]*W2[l][h][k]
            float4 b2a = *(const float4*)(b2 + l * 8);
            float4 b2b = *(const float4*)(b2 + l * 8 + 4);
            unsigned long long a2[4];
            a2[0] = pk2(b2a.x, b2a.y);
            a2[1] = pk2(b2a.z, b2a.w);
            a2[2] = pk2(b2b.x, b2b.y);
            a2[3] = pk2(b2b.z, b2b.w);
            const unsigned long long* w2p = (const unsigned long long*)(W2 + l * 64);
            #pragma unroll
            for (int hh = 0; hh < 8; ++hh) {
                unsigned long long hp = pk2(h1v[hh], h1v[hh]);
                fma2(a2[0], hp, w2p[hh * 4 + 0]);
                fma2(a2[1], hp, w2p[hh * 4 + 1]);
                fma2(a2[2], hp, w2p[hh * 4 + 2]);
                fma2(a2[3], hp, w2p[hh * 4 + 3]);
            }
            // layer 3
            float2 b3v = *(const float2*)(b3 + l * 2);
            float mu = b3v.x, al = b3v.y;
            const float4* w3p = (const float4*)(W3 + l * 16);
            #pragma unroll
            for (int qq = 0; qq < 4; ++qq) {
                float2 pr = up2(a2[qq]);
                float h2a = ftanha(pr.x), h2b = ftanha(pr.y);
                float4 wv = w3p[qq];
                mu += h2a * wv.x + h2b * wv.z;
                al += h2a * wv.y + h2b * wv.w;
            }
            float xn = x[(size_t)rowg * DD + (l + 1)];
            zst[row * 17 + (l & 15)] = (xn - mu) * __expf(-al);
            alacc += al;
        }
        if (jb & 1) {
            __syncthreads();
            int g = jb >> 1;
            #pragma unroll
            for (int i = 0; i < 2; ++i) {
                int v = i * 256 + tid;
                int r = v >> 4, lc = v & 15;
                int col = 254 - g * 16 - lc;
                if (col >= 0)
                    out[(size_t)(row0 + r) * DD + col] = zst[r * 17 + lc];
            }
            __syncthreads();
        }
    }

    // alpha reduce + finals
    als[tid] = alacc;
    __syncthreads();
    if (tid < 32) {
        float s = 0.f;
        #pragma unroll
        for (int qq = 0; qq < 8; ++qq) s += als[tid + 32 * qq];
        float ip0 = ipar[0], ip1 = ipar[1];
        out[(size_t)(row0 + tid) * DD + 255] =
            (x[(size_t)(row0 + tid) * DD] - ip0) * __expf(-ip1);
        if (out_size > BB * DD)
            out[(size_t)BB * DD + row0 + tid] = -(ip1 + s);
    }
}

extern "C" void kernel_launch(void* const* d_in, const int* in_sizes, int n_in,
                              void* d_out, int out_size)
{
    const float* x    = (const float*)d_in[0];
    const float* ipar = (const float*)d_in[1];
    const float* W1   = (const float*)d_in[2];
    const float* b1   = (const float*)d_in[3];
    const float* W2   = (const float*)d_in[4];
    const float* b2   = (const float*)d_in[5];
    const float* W3   = (const float*)d_in[6];
    const float* b3   = (const float*)d_in[7];
    float* out = (float*)d_out;

    prep_w1<<<dim3(16, 16), 256>>>(W1);
    prep_x<<<2048, 256>>>(x);
    cudaFuncSetAttribute(gemm_kernel, cudaFuncAttributeMaxDynamicSharedMemorySize, GEMM_SMEM);
    gemm_kernel<<<2048, 256, GEMM_SMEM>>>(b1);
    zmaf_kernel<<<BB / 32, 256>>>(x, ipar, W2, b2, W3, b3, out, out_size);
}